// round 13
// baseline (speedup 1.0000x reference)
#include <cuda_runtime.h>
#include <cuda_fp16.h>
#include <math.h>

#define N_USERS 100000
#define N_ITEMS 50000
#define BATCH   64
#define ORDER   8
#define FLATNESS 2
#define MAX_NNZ 1600000

#define SCAN_T 256
#define SCAN_E 8                     // 2048 elements per scan block
#define NBU ((N_USERS + SCAN_T*SCAN_E - 1) / (SCAN_T*SCAN_E))   // 49
#define NBI ((N_ITEMS + SCAN_T*SCAN_E - 1) / (SCAN_T*SCAN_E))   // 25
#define P3U ((N_USERS + 1023) / 1024)   // 98
#define P3I ((N_ITEMS + 1023) / 1024)   // 49

// ---------------- scratch (no allocation allowed -> device globals) ----------
__device__ float  g_ta [(size_t)N_ITEMS * BATCH];   // t0 / t2 ping (fp32 state)
__device__ float  g_tb [(size_t)N_ITEMS * BATCH];   // t1 pong (fp32 state)
__device__ float  g_acc[(size_t)N_ITEMS * BATCH];   // output accumulator (item-major)
__device__ __half g_yh [(size_t)N_USERS * BATCH];   // (1/du)-scaled user intermediate
__device__ __half g_th [(size_t)N_ITEMS * BATCH];   // di_is-scaled iterate shadow

__device__ int   g_ptru[N_USERS + 1];
__device__ int   g_ptri[N_ITEMS + 1];
__device__ int   g_curu[N_USERS];
__device__ int   g_curi[N_ITEMS];
__device__ int   g_part[128];                        // [0..63] user, [64..127] item
__device__ float g_dui[N_USERS];                     // 1/du  ( = du_is^2 )
__device__ float g_dis[N_ITEMS];                     // di^-1/2
__device__ int   g_evr[MAX_NNZ];                     // col indices sorted by row
__device__ int   g_evc[MAX_NNZ];                     // row indices sorted by col

// ---------------- transposes --------------------------------------------------
// signal [B][N] -> fp32 t0 [N][B]; half shadow pre-scaled by di_is
__global__ void transpose_in(const float* __restrict__ src, float* __restrict__ dst,
                             __half* __restrict__ dsth, const float* __restrict__ dis)
{
    __shared__ float tile[32][33];
    int i0 = blockIdx.x * 32, b0 = blockIdx.y * 32;
#pragma unroll
    for (int k = 0; k < 4; k++) {
        int b = b0 + threadIdx.y + k * 8, i = i0 + threadIdx.x;
        if (i < N_ITEMS) tile[threadIdx.y + k * 8][threadIdx.x] = src[(size_t)b * N_ITEMS + i];
    }
    __syncthreads();
#pragma unroll
    for (int k = 0; k < 4; k++) {
        int i = i0 + threadIdx.y + k * 8, b = b0 + threadIdx.x;
        if (i < N_ITEMS) {
            float v = tile[threadIdx.x][threadIdx.y + k * 8];
            dst [(size_t)i * BATCH + b] = v;
            dsth[(size_t)i * BATCH + b] = __float2half_rn(v * __ldg(&dis[i]));
        }
    }
}

__global__ void transpose_out(const float* __restrict__ src, float* __restrict__ dst)
{
    __shared__ float tile[32][33];
    int i0 = blockIdx.x * 32, b0 = blockIdx.y * 32;
#pragma unroll
    for (int k = 0; k < 4; k++) {
        int i = i0 + threadIdx.y + k * 8, b = b0 + threadIdx.x;
        if (i < N_ITEMS) tile[threadIdx.y + k * 8][threadIdx.x] = src[(size_t)i * BATCH + b];
    }
    __syncthreads();
#pragma unroll
    for (int k = 0; k < 4; k++) {
        int b = b0 + threadIdx.y + k * 8, i = i0 + threadIdx.x;
        if (i < N_ITEMS) dst[(size_t)b * N_ITEMS + i] = tile[threadIdx.x][threadIdx.y + k * 8];
    }
}

// ---------------- CSR/CSC build ----------------------------------------------
__global__ void hist_kernel(const int* __restrict__ row, const int* __restrict__ col,
                            int* __restrict__ degu, int* __restrict__ degi, int nnz)
{
    int e = blockIdx.x * blockDim.x + threadIdx.x;
    if (e >= nnz) return;
    atomicAdd(&degu[row[e]], 1);
    atomicAdd(&degi[col[e]], 1);
}

__device__ __forceinline__ void scan_p1_body(const int* __restrict__ deg,
                                             int* __restrict__ ptr,
                                             int* __restrict__ partial,
                                             int n, int blk)
{
    __shared__ int wsum[8];
    int base = blk * SCAN_T * SCAN_E + threadIdx.x * SCAN_E;
    int v[SCAN_E], t = 0;
#pragma unroll
    for (int k = 0; k < SCAN_E; k++) {
        int i = base + k;
        v[k] = (i < n) ? deg[i] : 0;
        t += v[k];
    }
    int lane = threadIdx.x & 31, wid = threadIdx.x >> 5;
    int s = t;
#pragma unroll
    for (int o = 1; o < 32; o <<= 1) {
        int u = __shfl_up_sync(0xffffffff, s, o);
        if (lane >= o) s += u;
    }
    if (lane == 31) wsum[wid] = s;
    __syncthreads();
    if (wid == 0) {
        int w = (lane < 8) ? wsum[lane] : 0;
#pragma unroll
        for (int o = 1; o < 8; o <<= 1) {
            int u = __shfl_up_sync(0xffffffff, w, o);
            if (lane >= o) w += u;
        }
        if (lane < 8) wsum[lane] = w;
    }
    __syncthreads();
    int run = s - t + (wid ? wsum[wid - 1] : 0);
#pragma unroll
    for (int k = 0; k < SCAN_E; k++) {
        int i = base + k;
        if (i < n) ptr[i] = run;
        run += v[k];
    }
    if (threadIdx.x == SCAN_T - 1) partial[blk] = wsum[7];
}

__global__ void scan_phase1_fused(const int* __restrict__ du, int* __restrict__ pu,
                                  const int* __restrict__ di, int* __restrict__ pi,
                                  int* __restrict__ partial)
{
    int b = blockIdx.x;
    if (b < NBU) scan_p1_body(du, pu, partial,      N_USERS, b);
    else         scan_p1_body(di, pi, partial + 64, N_ITEMS, b - NBU);
}

__device__ __forceinline__ void scan_p2_body(int* partial, int nb, int lane)
{
    int a = (lane < nb) ? partial[lane] : 0;
    int b = (lane + 32 < nb) ? partial[lane + 32] : 0;
    int sa = a, sb = b;
#pragma unroll
    for (int o = 1; o < 32; o <<= 1) {
        int u = __shfl_up_sync(0xffffffff, sa, o); if (lane >= o) sa += u;
        int w = __shfl_up_sync(0xffffffff, sb, o); if (lane >= o) sb += w;
    }
    int tot_a = __shfl_sync(0xffffffff, sa, 31);
    if (lane < nb)      partial[lane]      = sa - a;
    if (lane + 32 < nb) partial[lane + 32] = sb - b + tot_a;
}

__global__ void scan_phase2_fused(int* partial)
{
    int w = threadIdx.x >> 5, lane = threadIdx.x & 31;
    if (w == 0) scan_p2_body(partial,      NBU, lane);
    else        scan_p2_body(partial + 64, NBI, lane);
}

__device__ __forceinline__ void scan_p3_body(int* __restrict__ ptr, int* __restrict__ cursor,
                                             const int* __restrict__ partial,
                                             int n, int total, int blk)
{
    int i = blk * 1024 + threadIdx.x * 4;
    if (i < n) {
        int off = partial[i / (SCAN_T * SCAN_E)];
#pragma unroll
        for (int k = 0; k < 4; k++) {
            int j = i + k;
            if (j < n) { int p = ptr[j] + off; ptr[j] = p; cursor[j] = p; }
        }
    }
    if (blk == 0 && threadIdx.x == 0) ptr[n] = total;
}

__global__ void scan_phase3_fused(int* __restrict__ pu, int* __restrict__ cu,
                                  int* __restrict__ pi, int* __restrict__ ci,
                                  const int* __restrict__ partial, int nnz)
{
    int b = blockIdx.x;
    if (b < P3U) scan_p3_body(pu, cu, partial,      N_USERS, nnz, b);
    else         scan_p3_body(pi, ci, partial + 64, N_ITEMS, nnz, b - P3U);
}

// user scale = 1/du (du_is applied twice: once producing y, once as edge weight);
// item scale = di^-1/2
__global__ void scale_kernel(const int* __restrict__ pu, float* __restrict__ dui,
                             const int* __restrict__ pi, float* __restrict__ dis)
{
    int i = blockIdx.x * blockDim.x + threadIdx.x;
    if (i < N_USERS) {
        int d = pu[i + 1] - pu[i];
        dui[i] = (d > 0) ? 1.0f / (float)d : 0.f;
    }
    int k = i - N_USERS;
    if (k >= 0 && k < N_ITEMS) {
        int d = pi[k + 1] - pi[k];
        dis[k] = (d > 0) ? rsqrtf((float)d) : 0.f;
    }
}

__global__ void build_lists(const int* __restrict__ row, const int* __restrict__ col,
                            int* __restrict__ cu, int* __restrict__ ci,
                            int* __restrict__ evr, int* __restrict__ evc, int nnz)
{
    int e = blockIdx.x * blockDim.x + threadIdx.x;
    if (e >= nnz) return;
    int r = row[e], c = col[e];
    int pu = atomicAdd(&cu[r], 1);
    evr[pu] = c;
    int pc = atomicAdd(&ci[c], 1);
    evc[pc] = r;
}

// ---------------- wide gather core --------------------------------------------
// One warp per row. 8-lane groups: group g = lane>>3 handles edge j+g, slice
// sl = lane&7 covers halves [8sl, 8sl+8) of the 128B row. 4 edges per iter.
// Software-pipelined (prefetch depth 1): the next edge index is loaded BEFORE
// the current gather is consumed, so the ev-load latency hides under the
// gather latency instead of chaining with it.
struct Acc8 { float a[8]; };

__device__ __forceinline__ Acc8 gather_row(const __half* __restrict__ xh,
                                           const int* __restrict__ ev,
                                           int j0, int e, int g, int sl)
{
    Acc8 r;
#pragma unroll
    for (int k = 0; k < 8; k++) r.a[k] = 0.f;

    int j = j0 + g;
    if (j < e) {
        int idx = __ldg(&ev[j]);
        while (true) {
            int  jn   = j + 4;
            bool more = (jn < e);
            int  idxn = 0;
            if (more) idxn = __ldg(&ev[jn]);          // prefetch next index
            uint4 q = __ldg((const uint4*)(xh + ((size_t)idx << 6)) + sl);
            float2 f0 = __half22float2(*(__half2*)&q.x);
            float2 f1 = __half22float2(*(__half2*)&q.y);
            float2 f2 = __half22float2(*(__half2*)&q.z);
            float2 f3 = __half22float2(*(__half2*)&q.w);
            r.a[0] += f0.x; r.a[1] += f0.y;
            r.a[2] += f1.x; r.a[3] += f1.y;
            r.a[4] += f2.x; r.a[5] += f2.y;
            r.a[6] += f3.x; r.a[7] += f3.y;
            if (!more) break;
            j = jn; idx = idxn;
        }
    }
#pragma unroll
    for (int k = 0; k < 8; k++) {
        r.a[k] += __shfl_xor_sync(0xffffffff, r.a[k], 8);
        r.a[k] += __shfl_xor_sync(0xffffffff, r.a[k], 16);
    }
    return r;
}

__device__ __forceinline__ uint4 pack_half8_scaled(const Acc8& r, float s)
{
    uint4 o;
    *(__half2*)&o.x = __floats2half2_rn(s * r.a[0], s * r.a[1]);
    *(__half2*)&o.y = __floats2half2_rn(s * r.a[2], s * r.a[3]);
    *(__half2*)&o.z = __floats2half2_rn(s * r.a[4], s * r.a[5]);
    *(__half2*)&o.w = __floats2half2_rn(s * r.a[6], s * r.a[7]);
    return o;
}

// user side: yh[r] = half( (1/du[r]) * sum_j th[col_j] )
__global__ void __launch_bounds__(256) spmm_user(
    const __half* __restrict__ xh, __half* __restrict__ yh,
    const int* __restrict__ ev, const int* __restrict__ ptr,
    const float* __restrict__ dui)
{
    int r = blockIdx.x * 8 + (threadIdx.x >> 5);
    if (r >= N_USERS) return;
    int lane = threadIdx.x & 31, g = lane >> 3, sl = lane & 7;
    int j0 = __ldg(&ptr[r]), e = __ldg(&ptr[r + 1]);
    Acc8 s = gather_row(xh, ev, j0, e, g, sl);
    if (g == 0)
        ((uint4*)(yh + ((size_t)r << 6)))[sl] = pack_half8_scaled(s, __ldg(&dui[r]));
}

// item side, first lap: z = dis[r]*sum(yh); t1 = t0 - 2z; acc = c0*t0 + c1*t1;
// th = half(dis[r]*t1)
__global__ void __launch_bounds__(256) spmm_item_first(
    const __half* __restrict__ yh, const int* __restrict__ ev, const int* __restrict__ ptr,
    const float* __restrict__ t0, float* __restrict__ t1, float* __restrict__ acc,
    __half* __restrict__ th, const float* __restrict__ dis, float c0, float c1)
{
    int r = blockIdx.x * 8 + (threadIdx.x >> 5);
    if (r >= N_ITEMS) return;
    int lane = threadIdx.x & 31, g = lane >> 3, sl = lane & 7;
    int j0 = __ldg(&ptr[r]), e = __ldg(&ptr[r + 1]);
    Acc8 z = gather_row(yh, ev, j0, e, g, sl);
    if (g == 0) {
        float d = __ldg(&dis[r]);
        size_t o = ((size_t)r << 6) + (size_t)sl * 8;
        Acc8 b;
#pragma unroll
        for (int h = 0; h < 2; h++) {
            float4 a = *(const float4*)(t0 + o + h * 4);
            float4 bb, oo;
            bb.x = a.x - 2.f * (d * z.a[h*4+0]); bb.y = a.y - 2.f * (d * z.a[h*4+1]);
            bb.z = a.z - 2.f * (d * z.a[h*4+2]); bb.w = a.w - 2.f * (d * z.a[h*4+3]);
            *(float4*)(t1 + o + h * 4) = bb;
            oo.x = c0 * a.x + c1 * bb.x; oo.y = c0 * a.y + c1 * bb.y;
            oo.z = c0 * a.z + c1 * bb.z; oo.w = c0 * a.w + c1 * bb.w;
            *(float4*)(acc + o + h * 4) = oo;
            b.a[h*4+0] = bb.x; b.a[h*4+1] = bb.y; b.a[h*4+2] = bb.z; b.a[h*4+3] = bb.w;
        }
        *(uint4*)(th + o) = pack_half8_scaled(b, d);
    }
}

// item side, step: z = dis[r]*sum(yh); t2 = 2*t1 - 4z - t0 (in place over t0);
// if do_acc: acc += ca*t1 + cb*t2 ; if !last: write t0io, th = half(dis*t2)
__global__ void __launch_bounds__(256) spmm_item_step(
    const __half* __restrict__ yh, const int* __restrict__ ev, const int* __restrict__ ptr,
    float* __restrict__ t0io, const float* __restrict__ t1, float* __restrict__ acc,
    __half* __restrict__ th, const float* __restrict__ dis,
    float ca, float cb, int do_acc, int last)
{
    int r = blockIdx.x * 8 + (threadIdx.x >> 5);
    if (r >= N_ITEMS) return;
    int lane = threadIdx.x & 31, g = lane >> 3, sl = lane & 7;
    int j0 = __ldg(&ptr[r]), e = __ldg(&ptr[r + 1]);
    Acc8 z = gather_row(yh, ev, j0, e, g, sl);
    if (g == 0) {
        float d = __ldg(&dis[r]);
        size_t o = ((size_t)r << 6) + (size_t)sl * 8;
        Acc8 t2;
#pragma unroll
        for (int h = 0; h < 2; h++) {
            float4 a = *(const float4*)(t0io + o + h * 4);
            float4 b = *(const float4*)(t1 + o + h * 4);
            float4 t;
            t.x = 2.f * b.x - 4.f * (d * z.a[h*4+0]) - a.x;
            t.y = 2.f * b.y - 4.f * (d * z.a[h*4+1]) - a.y;
            t.z = 2.f * b.z - 4.f * (d * z.a[h*4+2]) - a.z;
            t.w = 2.f * b.w - 4.f * (d * z.a[h*4+3]) - a.w;
            if (!last) *(float4*)(t0io + o + h * 4) = t;
            if (do_acc) {
                float4 oc = *(const float4*)(acc + o + h * 4);
                oc.x += ca * b.x + cb * t.x;
                oc.y += ca * b.y + cb * t.y;
                oc.z += ca * b.z + cb * t.z;
                oc.w += ca * b.w + cb * t.w;
                *(float4*)(acc + o + h * 4) = oc;
            }
            t2.a[h*4+0] = t.x; t2.a[h*4+1] = t.y; t2.a[h*4+2] = t.z; t2.a[h*4+3] = t.w;
        }
        if (!last) *(uint4*)(th + o) = pack_half8_scaled(t2, d);
    }
}

// ---------------- host: replicate cheby_coeffs in double ----------------------
static void compute_coeffs(float c[ORDER + 1])
{
    const int order = ORDER;
    double tgt[ORDER + 1], nodes[ORDER + 1];
    for (int x = 0; x <= order; x++) {
        double v = cos((double)(order - x) / order * M_PI);
        v = nearbyint(v * 1000.0) / 1000.0;
        double t = (v < 0.0) ? pow(-v, (double)FLATNESS) * 0.5 + 0.5
                             : pow(v, (double)FLATNESS) * (-0.5) + 0.5;
        tgt[x] = nearbyint(t * 1000.0) / 1000.0;
    }
    for (int k = 1; k <= order + 1; k++)
        nodes[k - 1] = cos((order + 1 + 0.5 - k) / (double)(order + 1) * M_PI);

    double P0[ORDER + 1], P1[ORDER + 1], P2[ORDER + 1];
    double s0 = 0.0, s1 = 0.0;
    for (int i = 0; i <= order; i++) {
        P0[i] = tgt[i];
        P1[i] = nodes[i] * tgt[i];
        s0 += P0[i]; s1 += P1[i];
    }
    c[0] = (float)(s0 * (2.0 / (order + 1)) / 2.0);
    c[1] = (float)(s1 * (2.0 / (order + 1)));
    for (int k = 2; k <= order; k++) {
        double s = 0.0;
        for (int i = 0; i <= order; i++) {
            P2[i] = 2.0 * nodes[i] * P1[i] - P0[i];
            s += P2[i];
        }
        c[k] = (float)(s * (2.0 / (order + 1)));
        for (int i = 0; i <= order; i++) { P0[i] = P1[i]; P1[i] = P2[i]; }
    }
}

// ---------------- launch ------------------------------------------------------
extern "C" void kernel_launch(void* const* d_in, const int* in_sizes, int n_in,
                              void* d_out, int out_size)
{
    const float* signal = (const float*)d_in[0];
    const int*   row    = (const int*)d_in[2];
    const int*   col    = (const int*)d_in[3];
    const int    nnz    = in_sizes[1];

    float c[ORDER + 1];
    compute_coeffs(c);

    float *ta, *tb, *acc, *dui, *dis;
    __half *yh, *th;
    int *ptru, *ptri, *curu, *curi, *part, *evr, *evc;
    cudaGetSymbolAddress((void**)&ta,   g_ta);
    cudaGetSymbolAddress((void**)&tb,   g_tb);
    cudaGetSymbolAddress((void**)&acc,  g_acc);
    cudaGetSymbolAddress((void**)&yh,   g_yh);
    cudaGetSymbolAddress((void**)&th,   g_th);
    cudaGetSymbolAddress((void**)&ptru, g_ptru);
    cudaGetSymbolAddress((void**)&ptri, g_ptri);
    cudaGetSymbolAddress((void**)&curu, g_curu);
    cudaGetSymbolAddress((void**)&curi, g_curi);
    cudaGetSymbolAddress((void**)&part, g_part);
    cudaGetSymbolAddress((void**)&dui,  g_dui);
    cudaGetSymbolAddress((void**)&dis,  g_dis);
    cudaGetSymbolAddress((void**)&evr,  g_evr);
    cudaGetSymbolAddress((void**)&evc,  g_evc);

    dim3 tblk(32, 8);
    dim3 tgrd((N_ITEMS + 31) / 32, (BATCH + 31) / 32);

    const int eblk = (nnz + 255) / 256;
    const int gu   = (N_USERS + 7) / 8;
    const int gi   = (N_ITEMS + 7) / 8;
    const int sblk = (N_USERS + N_ITEMS + 255) / 256;

    // ---- preprocessing: CSR (by user) + CSC (by item), fused scans ----
    cudaMemsetAsync(curu, 0, sizeof(int) * N_USERS);
    cudaMemsetAsync(curi, 0, sizeof(int) * N_ITEMS);
    hist_kernel<<<eblk, 256>>>(row, col, curu, curi, nnz);
    scan_phase1_fused<<<NBU + NBI, SCAN_T>>>(curu, ptru, curi, ptri, part);
    scan_phase2_fused<<<1, 64>>>(part);
    scan_phase3_fused<<<P3U + P3I, SCAN_T>>>(ptru, curu, ptri, curi, part, nnz);
    scale_kernel<<<sblk, 256>>>(ptru, dui, ptri, dis);
    build_lists<<<eblk, 256>>>(row, col, curu, curi, evr, evc, nnz);

    // ---- signal to item-major (fp32 state + di_is-scaled half shadow) ----
    transpose_in<<<tgrd, tblk>>>(signal, ta, th, dis);

    // ---- Chebyshev recurrence, 8 laps ----
    spmm_user<<<gu, 256>>>(th, yh, evr, ptru, dui);
    spmm_item_first<<<gi, 256>>>(yh, evc, ptri, ta, tb, acc, th, dis, c[0], c[1]);

    float* p0 = ta;   // t_{k-2}
    float* p1 = tb;   // t_{k-1}
    for (int k = 2; k <= ORDER; k++) {
        spmm_user<<<gu, 256>>>(th, yh, evr, ptru, dui);
        int   last   = (k == ORDER);
        int   pair   = (k & 1);               // odd step: fold in c[k-1]*t1 too
        int   do_acc = pair || last;
        float ca     = pair ? c[k - 1] : 0.f;
        float cb     = do_acc ? c[k] : 0.f;
        spmm_item_step<<<gi, 256>>>(yh, evc, ptri, p0, p1, acc, th, dis,
                                    ca, cb, do_acc, last);
        float* t = p0; p0 = p1; p1 = t;
    }

    transpose_out<<<tgrd, tblk>>>(acc, (float*)d_out);
}

// round 14
// speedup vs baseline: 1.0393x; 1.0393x over previous
#include <cuda_runtime.h>
#include <cuda_fp16.h>
#include <math.h>

#define N_USERS 100000
#define N_ITEMS 50000
#define BATCH   64
#define ORDER   8
#define FLATNESS 2
#define MAX_NNZ 1600000

#define SCAN_T 256
#define SCAN_E 8                     // 2048 elements per scan block
#define NBU ((N_USERS + SCAN_T*SCAN_E - 1) / (SCAN_T*SCAN_E))   // 49
#define NBI ((N_ITEMS + SCAN_T*SCAN_E - 1) / (SCAN_T*SCAN_E))   // 25
#define P3U ((N_USERS + 1023) / 1024)   // 98
#define P3I ((N_ITEMS + 1023) / 1024)   // 49

// SpMM block shape: 128 threads = 4 warps = 4 rows per CTA (tail reduction)
#define SPMM_T 128
#define SPMM_ROWS 4

// ---------------- scratch (no allocation allowed -> device globals) ----------
__device__ float  g_ta [(size_t)N_ITEMS * BATCH];   // t0 / t2 ping (fp32 state)
__device__ float  g_tb [(size_t)N_ITEMS * BATCH];   // t1 pong (fp32 state)
__device__ float  g_acc[(size_t)N_ITEMS * BATCH];   // output accumulator (item-major)
__device__ __half g_yh [(size_t)N_USERS * BATCH];   // (1/du)-scaled user intermediate
__device__ __half g_th [(size_t)N_ITEMS * BATCH];   // di_is-scaled iterate shadow

__device__ int   g_ptru[N_USERS + 1];
__device__ int   g_ptri[N_ITEMS + 1];
__device__ int   g_curu[N_USERS];
__device__ int   g_curi[N_ITEMS];
__device__ int   g_part[128];                        // [0..63] user, [64..127] item
__device__ float g_dui[N_USERS];                     // 1/du  ( = du_is^2 )
__device__ float g_dis[N_ITEMS];                     // di^-1/2
__device__ int   g_evr[MAX_NNZ];                     // col indices sorted by row
__device__ int   g_evc[MAX_NNZ];                     // row indices sorted by col

// ---------------- transposes --------------------------------------------------
__global__ void transpose_in(const float* __restrict__ src, float* __restrict__ dst,
                             __half* __restrict__ dsth, const float* __restrict__ dis)
{
    __shared__ float tile[32][33];
    int i0 = blockIdx.x * 32, b0 = blockIdx.y * 32;
#pragma unroll
    for (int k = 0; k < 4; k++) {
        int b = b0 + threadIdx.y + k * 8, i = i0 + threadIdx.x;
        if (i < N_ITEMS) tile[threadIdx.y + k * 8][threadIdx.x] = src[(size_t)b * N_ITEMS + i];
    }
    __syncthreads();
#pragma unroll
    for (int k = 0; k < 4; k++) {
        int i = i0 + threadIdx.y + k * 8, b = b0 + threadIdx.x;
        if (i < N_ITEMS) {
            float v = tile[threadIdx.x][threadIdx.y + k * 8];
            dst [(size_t)i * BATCH + b] = v;
            dsth[(size_t)i * BATCH + b] = __float2half_rn(v * __ldg(&dis[i]));
        }
    }
}

__global__ void transpose_out(const float* __restrict__ src, float* __restrict__ dst)
{
    __shared__ float tile[32][33];
    int i0 = blockIdx.x * 32, b0 = blockIdx.y * 32;
#pragma unroll
    for (int k = 0; k < 4; k++) {
        int i = i0 + threadIdx.y + k * 8, b = b0 + threadIdx.x;
        if (i < N_ITEMS) tile[threadIdx.y + k * 8][threadIdx.x] = src[(size_t)i * BATCH + b];
    }
    __syncthreads();
#pragma unroll
    for (int k = 0; k < 4; k++) {
        int b = b0 + threadIdx.y + k * 8, i = i0 + threadIdx.x;
        if (i < N_ITEMS) dst[(size_t)b * N_ITEMS + i] = tile[threadIdx.x][threadIdx.y + k * 8];
    }
}

// ---------------- CSR/CSC build ----------------------------------------------
__global__ void hist_kernel(const int* __restrict__ row, const int* __restrict__ col,
                            int* __restrict__ degu, int* __restrict__ degi, int nnz)
{
    int e = blockIdx.x * blockDim.x + threadIdx.x;
    if (e >= nnz) return;
    atomicAdd(&degu[row[e]], 1);
    atomicAdd(&degi[col[e]], 1);
}

__device__ __forceinline__ void scan_p1_body(const int* __restrict__ deg,
                                             int* __restrict__ ptr,
                                             int* __restrict__ partial,
                                             int n, int blk)
{
    __shared__ int wsum[8];
    int base = blk * SCAN_T * SCAN_E + threadIdx.x * SCAN_E;
    int v[SCAN_E], t = 0;
#pragma unroll
    for (int k = 0; k < SCAN_E; k++) {
        int i = base + k;
        v[k] = (i < n) ? deg[i] : 0;
        t += v[k];
    }
    int lane = threadIdx.x & 31, wid = threadIdx.x >> 5;
    int s = t;
#pragma unroll
    for (int o = 1; o < 32; o <<= 1) {
        int u = __shfl_up_sync(0xffffffff, s, o);
        if (lane >= o) s += u;
    }
    if (lane == 31) wsum[wid] = s;
    __syncthreads();
    if (wid == 0) {
        int w = (lane < 8) ? wsum[lane] : 0;
#pragma unroll
        for (int o = 1; o < 8; o <<= 1) {
            int u = __shfl_up_sync(0xffffffff, w, o);
            if (lane >= o) w += u;
        }
        if (lane < 8) wsum[lane] = w;
    }
    __syncthreads();
    int run = s - t + (wid ? wsum[wid - 1] : 0);
#pragma unroll
    for (int k = 0; k < SCAN_E; k++) {
        int i = base + k;
        if (i < n) ptr[i] = run;
        run += v[k];
    }
    if (threadIdx.x == SCAN_T - 1) partial[blk] = wsum[7];
}

__global__ void scan_phase1_fused(const int* __restrict__ du, int* __restrict__ pu,
                                  const int* __restrict__ di, int* __restrict__ pi,
                                  int* __restrict__ partial)
{
    int b = blockIdx.x;
    if (b < NBU) scan_p1_body(du, pu, partial,      N_USERS, b);
    else         scan_p1_body(di, pi, partial + 64, N_ITEMS, b - NBU);
}

__device__ __forceinline__ void scan_p2_body(int* partial, int nb, int lane)
{
    int a = (lane < nb) ? partial[lane] : 0;
    int b = (lane + 32 < nb) ? partial[lane + 32] : 0;
    int sa = a, sb = b;
#pragma unroll
    for (int o = 1; o < 32; o <<= 1) {
        int u = __shfl_up_sync(0xffffffff, sa, o); if (lane >= o) sa += u;
        int w = __shfl_up_sync(0xffffffff, sb, o); if (lane >= o) sb += w;
    }
    int tot_a = __shfl_sync(0xffffffff, sa, 31);
    if (lane < nb)      partial[lane]      = sa - a;
    if (lane + 32 < nb) partial[lane + 32] = sb - b + tot_a;
}

__global__ void scan_phase2_fused(int* partial)
{
    int w = threadIdx.x >> 5, lane = threadIdx.x & 31;
    if (w == 0) scan_p2_body(partial,      NBU, lane);
    else        scan_p2_body(partial + 64, NBI, lane);
}

__device__ __forceinline__ void scan_p3_body(int* __restrict__ ptr, int* __restrict__ cursor,
                                             const int* __restrict__ partial,
                                             int n, int total, int blk)
{
    int i = blk * 1024 + threadIdx.x * 4;
    if (i < n) {
        int off = partial[i / (SCAN_T * SCAN_E)];
#pragma unroll
        for (int k = 0; k < 4; k++) {
            int j = i + k;
            if (j < n) { int p = ptr[j] + off; ptr[j] = p; cursor[j] = p; }
        }
    }
    if (blk == 0 && threadIdx.x == 0) ptr[n] = total;
}

__global__ void scan_phase3_fused(int* __restrict__ pu, int* __restrict__ cu,
                                  int* __restrict__ pi, int* __restrict__ ci,
                                  const int* __restrict__ partial, int nnz)
{
    int b = blockIdx.x;
    if (b < P3U) scan_p3_body(pu, cu, partial,      N_USERS, nnz, b);
    else         scan_p3_body(pi, ci, partial + 64, N_ITEMS, nnz, b - P3U);
}

// user scale = 1/du (du_is applied twice); item scale = di^-1/2
__global__ void scale_kernel(const int* __restrict__ pu, float* __restrict__ dui,
                             const int* __restrict__ pi, float* __restrict__ dis)
{
    int i = blockIdx.x * blockDim.x + threadIdx.x;
    if (i < N_USERS) {
        int d = pu[i + 1] - pu[i];
        dui[i] = (d > 0) ? 1.0f / (float)d : 0.f;
    }
    int k = i - N_USERS;
    if (k >= 0 && k < N_ITEMS) {
        int d = pi[k + 1] - pi[k];
        dis[k] = (d > 0) ? rsqrtf((float)d) : 0.f;
    }
}

__global__ void build_lists(const int* __restrict__ row, const int* __restrict__ col,
                            int* __restrict__ cu, int* __restrict__ ci,
                            int* __restrict__ evr, int* __restrict__ evc, int nnz)
{
    int e = blockIdx.x * blockDim.x + threadIdx.x;
    if (e >= nnz) return;
    int r = row[e], c = col[e];
    int pu = atomicAdd(&cu[r], 1);
    evr[pu] = c;
    int pc = atomicAdd(&ci[c], 1);
    evc[pc] = r;
}

// ---------------- wide gather core --------------------------------------------
// One warp per row. 8-lane groups: group g = lane>>3 handles edge j+g, slice
// sl = lane&7 covers halves [8sl, 8sl+8) of the 128B row. 4 edges per iter,
// unroll 2 (R4/R6-proven; deeper unroll and sw-pipelining both regressed).
struct Acc8 { float a[8]; };

__device__ __forceinline__ Acc8 gather_row(const __half* __restrict__ xh,
                                           const int* __restrict__ ev,
                                           int j0, int e, int g, int sl)
{
    Acc8 r;
#pragma unroll
    for (int k = 0; k < 8; k++) r.a[k] = 0.f;
#pragma unroll 2
    for (int j = j0 + g; j < e; j += 4) {
        int idx = __ldg(&ev[j]);
        uint4 q = __ldg((const uint4*)(xh + ((size_t)idx << 6)) + sl);
        float2 f0 = __half22float2(*(__half2*)&q.x);
        float2 f1 = __half22float2(*(__half2*)&q.y);
        float2 f2 = __half22float2(*(__half2*)&q.z);
        float2 f3 = __half22float2(*(__half2*)&q.w);
        r.a[0] += f0.x; r.a[1] += f0.y;
        r.a[2] += f1.x; r.a[3] += f1.y;
        r.a[4] += f2.x; r.a[5] += f2.y;
        r.a[6] += f3.x; r.a[7] += f3.y;
    }
#pragma unroll
    for (int k = 0; k < 8; k++) {
        r.a[k] += __shfl_xor_sync(0xffffffff, r.a[k], 8);
        r.a[k] += __shfl_xor_sync(0xffffffff, r.a[k], 16);
    }
    return r;
}

__device__ __forceinline__ uint4 pack_half8_scaled(const Acc8& r, float s)
{
    uint4 o;
    *(__half2*)&o.x = __floats2half2_rn(s * r.a[0], s * r.a[1]);
    *(__half2*)&o.y = __floats2half2_rn(s * r.a[2], s * r.a[3]);
    *(__half2*)&o.z = __floats2half2_rn(s * r.a[4], s * r.a[5]);
    *(__half2*)&o.w = __floats2half2_rn(s * r.a[6], s * r.a[7]);
    return o;
}

// user side: yh[r] = half( (1/du[r]) * sum_j th[col_j] )
__global__ void __launch_bounds__(SPMM_T) spmm_user(
    const __half* __restrict__ xh, __half* __restrict__ yh,
    const int* __restrict__ ev, const int* __restrict__ ptr,
    const float* __restrict__ dui)
{
    int r = blockIdx.x * SPMM_ROWS + (threadIdx.x >> 5);
    if (r >= N_USERS) return;
    int lane = threadIdx.x & 31, g = lane >> 3, sl = lane & 7;
    int j0 = __ldg(&ptr[r]), e = __ldg(&ptr[r + 1]);
    Acc8 s = gather_row(xh, ev, j0, e, g, sl);
    if (g == 0)
        ((uint4*)(yh + ((size_t)r << 6)))[sl] = pack_half8_scaled(s, __ldg(&dui[r]));
}

// item side, first lap: z = dis[r]*sum(yh); t1 = t0 - 2z; acc = c0*t0 + c1*t1;
// th = half(dis[r]*t1)
__global__ void __launch_bounds__(SPMM_T) spmm_item_first(
    const __half* __restrict__ yh, const int* __restrict__ ev, const int* __restrict__ ptr,
    const float* __restrict__ t0, float* __restrict__ t1, float* __restrict__ acc,
    __half* __restrict__ th, const float* __restrict__ dis, float c0, float c1)
{
    int r = blockIdx.x * SPMM_ROWS + (threadIdx.x >> 5);
    if (r >= N_ITEMS) return;
    int lane = threadIdx.x & 31, g = lane >> 3, sl = lane & 7;
    int j0 = __ldg(&ptr[r]), e = __ldg(&ptr[r + 1]);
    Acc8 z = gather_row(yh, ev, j0, e, g, sl);
    if (g == 0) {
        float d = __ldg(&dis[r]);
        size_t o = ((size_t)r << 6) + (size_t)sl * 8;
        Acc8 b;
#pragma unroll
        for (int h = 0; h < 2; h++) {
            float4 a = *(const float4*)(t0 + o + h * 4);
            float4 bb, oo;
            bb.x = a.x - 2.f * (d * z.a[h*4+0]); bb.y = a.y - 2.f * (d * z.a[h*4+1]);
            bb.z = a.z - 2.f * (d * z.a[h*4+2]); bb.w = a.w - 2.f * (d * z.a[h*4+3]);
            *(float4*)(t1 + o + h * 4) = bb;
            oo.x = c0 * a.x + c1 * bb.x; oo.y = c0 * a.y + c1 * bb.y;
            oo.z = c0 * a.z + c1 * bb.z; oo.w = c0 * a.w + c1 * bb.w;
            *(float4*)(acc + o + h * 4) = oo;
            b.a[h*4+0] = bb.x; b.a[h*4+1] = bb.y; b.a[h*4+2] = bb.z; b.a[h*4+3] = bb.w;
        }
        *(uint4*)(th + o) = pack_half8_scaled(b, d);
    }
}

// item side, step: z = dis[r]*sum(yh); t2 = 2*t1 - 4z - t0 (in place over t0);
// if do_acc: acc += ca*t1 + cb*t2 ; if !last: write t0io, th = half(dis*t2)
__global__ void __launch_bounds__(SPMM_T) spmm_item_step(
    const __half* __restrict__ yh, const int* __restrict__ ev, const int* __restrict__ ptr,
    float* __restrict__ t0io, const float* __restrict__ t1, float* __restrict__ acc,
    __half* __restrict__ th, const float* __restrict__ dis,
    float ca, float cb, int do_acc, int last)
{
    int r = blockIdx.x * SPMM_ROWS + (threadIdx.x >> 5);
    if (r >= N_ITEMS) return;
    int lane = threadIdx.x & 31, g = lane >> 3, sl = lane & 7;
    int j0 = __ldg(&ptr[r]), e = __ldg(&ptr[r + 1]);
    Acc8 z = gather_row(yh, ev, j0, e, g, sl);
    if (g == 0) {
        float d = __ldg(&dis[r]);
        size_t o = ((size_t)r << 6) + (size_t)sl * 8;
        Acc8 t2;
#pragma unroll
        for (int h = 0; h < 2; h++) {
            float4 a = *(const float4*)(t0io + o + h * 4);
            float4 b = *(const float4*)(t1 + o + h * 4);
            float4 t;
            t.x = 2.f * b.x - 4.f * (d * z.a[h*4+0]) - a.x;
            t.y = 2.f * b.y - 4.f * (d * z.a[h*4+1]) - a.y;
            t.z = 2.f * b.z - 4.f * (d * z.a[h*4+2]) - a.z;
            t.w = 2.f * b.w - 4.f * (d * z.a[h*4+3]) - a.w;
            if (!last) *(float4*)(t0io + o + h * 4) = t;
            if (do_acc) {
                float4 oc = *(const float4*)(acc + o + h * 4);
                oc.x += ca * b.x + cb * t.x;
                oc.y += ca * b.y + cb * t.y;
                oc.z += ca * b.z + cb * t.z;
                oc.w += ca * b.w + cb * t.w;
                *(float4*)(acc + o + h * 4) = oc;
            }
            t2.a[h*4+0] = t.x; t2.a[h*4+1] = t.y; t2.a[h*4+2] = t.z; t2.a[h*4+3] = t.w;
        }
        if (!last) *(uint4*)(th + o) = pack_half8_scaled(t2, d);
    }
}

// ---------------- host: replicate cheby_coeffs in double ----------------------
static void compute_coeffs(float c[ORDER + 1])
{
    const int order = ORDER;
    double tgt[ORDER + 1], nodes[ORDER + 1];
    for (int x = 0; x <= order; x++) {
        double v = cos((double)(order - x) / order * M_PI);
        v = nearbyint(v * 1000.0) / 1000.0;
        double t = (v < 0.0) ? pow(-v, (double)FLATNESS) * 0.5 + 0.5
                             : pow(v, (double)FLATNESS) * (-0.5) + 0.5;
        tgt[x] = nearbyint(t * 1000.0) / 1000.0;
    }
    for (int k = 1; k <= order + 1; k++)
        nodes[k - 1] = cos((order + 1 + 0.5 - k) / (double)(order + 1) * M_PI);

    double P0[ORDER + 1], P1[ORDER + 1], P2[ORDER + 1];
    double s0 = 0.0, s1 = 0.0;
    for (int i = 0; i <= order; i++) {
        P0[i] = tgt[i];
        P1[i] = nodes[i] * tgt[i];
        s0 += P0[i]; s1 += P1[i];
    }
    c[0] = (float)(s0 * (2.0 / (order + 1)) / 2.0);
    c[1] = (float)(s1 * (2.0 / (order + 1)));
    for (int k = 2; k <= order; k++) {
        double s = 0.0;
        for (int i = 0; i <= order; i++) {
            P2[i] = 2.0 * nodes[i] * P1[i] - P0[i];
            s += P2[i];
        }
        c[k] = (float)(s * (2.0 / (order + 1)));
        for (int i = 0; i <= order; i++) { P0[i] = P1[i]; P1[i] = P2[i]; }
    }
}

// ---------------- launch ------------------------------------------------------
extern "C" void kernel_launch(void* const* d_in, const int* in_sizes, int n_in,
                              void* d_out, int out_size)
{
    const float* signal = (const float*)d_in[0];
    const int*   row    = (const int*)d_in[2];
    const int*   col    = (const int*)d_in[3];
    const int    nnz    = in_sizes[1];

    float c[ORDER + 1];
    compute_coeffs(c);

    float *ta, *tb, *acc, *dui, *dis;
    __half *yh, *th;
    int *ptru, *ptri, *curu, *curi, *part, *evr, *evc;
    cudaGetSymbolAddress((void**)&ta,   g_ta);
    cudaGetSymbolAddress((void**)&tb,   g_tb);
    cudaGetSymbolAddress((void**)&acc,  g_acc);
    cudaGetSymbolAddress((void**)&yh,   g_yh);
    cudaGetSymbolAddress((void**)&th,   g_th);
    cudaGetSymbolAddress((void**)&ptru, g_ptru);
    cudaGetSymbolAddress((void**)&ptri, g_ptri);
    cudaGetSymbolAddress((void**)&curu, g_curu);
    cudaGetSymbolAddress((void**)&curi, g_curi);
    cudaGetSymbolAddress((void**)&part, g_part);
    cudaGetSymbolAddress((void**)&dui,  g_dui);
    cudaGetSymbolAddress((void**)&dis,  g_dis);
    cudaGetSymbolAddress((void**)&evr,  g_evr);
    cudaGetSymbolAddress((void**)&evc,  g_evc);

    dim3 tblk(32, 8);
    dim3 tgrd((N_ITEMS + 31) / 32, (BATCH + 31) / 32);

    const int eblk = (nnz + 255) / 256;
    const int gu   = (N_USERS + SPMM_ROWS - 1) / SPMM_ROWS;
    const int gi   = (N_ITEMS + SPMM_ROWS - 1) / SPMM_ROWS;
    const int sblk = (N_USERS + N_ITEMS + 255) / 256;

    // ---- preprocessing: CSR (by user) + CSC (by item), fused scans ----
    cudaMemsetAsync(curu, 0, sizeof(int) * N_USERS);
    cudaMemsetAsync(curi, 0, sizeof(int) * N_ITEMS);
    hist_kernel<<<eblk, 256>>>(row, col, curu, curi, nnz);
    scan_phase1_fused<<<NBU + NBI, SCAN_T>>>(curu, ptru, curi, ptri, part);
    scan_phase2_fused<<<1, 64>>>(part);
    scan_phase3_fused<<<P3U + P3I, SCAN_T>>>(ptru, curu, ptri, curi, part, nnz);
    scale_kernel<<<sblk, 256>>>(ptru, dui, ptri, dis);
    build_lists<<<eblk, 256>>>(row, col, curu, curi, evr, evc, nnz);

    // ---- signal to item-major (fp32 state + di_is-scaled half shadow) ----
    transpose_in<<<tgrd, tblk>>>(signal, ta, th, dis);

    // ---- Chebyshev recurrence, 8 laps ----
    spmm_user<<<gu, SPMM_T>>>(th, yh, evr, ptru, dui);
    spmm_item_first<<<gi, SPMM_T>>>(yh, evc, ptri, ta, tb, acc, th, dis, c[0], c[1]);

    float* p0 = ta;   // t_{k-2}
    float* p1 = tb;   // t_{k-1}
    for (int k = 2; k <= ORDER; k++) {
        spmm_user<<<gu, SPMM_T>>>(th, yh, evr, ptru, dui);
        int   last   = (k == ORDER);
        int   pair   = (k & 1);               // odd step: fold in c[k-1]*t1 too
        int   do_acc = pair || last;
        float ca     = pair ? c[k - 1] : 0.f;
        float cb     = do_acc ? c[k] : 0.f;
        spmm_item_step<<<gi, SPMM_T>>>(yh, evc, ptri, p0, p1, acc, th, dis,
                                       ca, cb, do_acc, last);
        float* t = p0; p0 = p1; p1 = t;
    }

    transpose_out<<<tgrd, tblk>>>(acc, (float*)d_out);
}

// round 16
// speedup vs baseline: 1.0464x; 1.0068x over previous
#include <cuda_runtime.h>
#include <cuda_fp16.h>
#include <math.h>

#define N_USERS 100000
#define N_ITEMS 50000
#define BATCH   64
#define ORDER   8
#define FLATNESS 2
#define MAX_NNZ 1600000

#define SCAN_T 256
#define SCAN_E 8                     // 2048 elements per scan block
#define NBU ((N_USERS + SCAN_T*SCAN_E - 1) / (SCAN_T*SCAN_E))   // 49
#define NBI ((N_ITEMS + SCAN_T*SCAN_E - 1) / (SCAN_T*SCAN_E))   // 25
#define P3U ((N_USERS + 1023) / 1024)   // 98
#define P3I ((N_ITEMS + 1023) / 1024)   // 49

// SpMM block shape: 128 threads = 4 warps = 4 rows per CTA
#define SPMM_T 128
#define SPMM_ROWS 4

// ---------------- scratch (no allocation allowed -> device globals) ----------
__device__ float  g_ta [(size_t)N_ITEMS * BATCH];   // t0 / t2 ping (fp32 state)
__device__ float  g_tb [(size_t)N_ITEMS * BATCH];   // t1 pong (fp32 state)
__device__ float  g_acc[(size_t)N_ITEMS * BATCH];   // output accumulator (item-major)
__device__ __half g_yh [(size_t)N_USERS * BATCH];   // (1/du)-scaled user intermediate
__device__ __half g_th [(size_t)N_ITEMS * BATCH];   // di_is-scaled iterate shadow

__device__ int   g_ptru[N_USERS + 1];
__device__ int   g_ptri[N_ITEMS + 1];
__device__ int   g_curu[N_USERS];
__device__ int   g_curi[N_ITEMS];
__device__ int   g_part[128];                        // [0..63] user, [64..127] item
__device__ float g_dui[N_USERS];                     // 1/du  ( = du_is^2 )
__device__ float g_dis[N_ITEMS];                     // di^-1/2
__device__ int   g_evr[MAX_NNZ];                     // col indices sorted by row
__device__ int   g_evc[MAX_NNZ];                     // row indices sorted by col

// degree-sort scratch: per-block 256-bin histograms -> offsets, and permutations
__device__ int   g_lhu[NBU * 256];
__device__ int   g_lhi[NBI * 256];
__device__ int   g_permu[N_USERS];
__device__ int   g_permi[N_ITEMS];

// ---------------- transposes --------------------------------------------------
__global__ void transpose_in(const float* __restrict__ src, float* __restrict__ dst,
                             __half* __restrict__ dsth, const float* __restrict__ dis)
{
    __shared__ float tile[32][33];
    int i0 = blockIdx.x * 32, b0 = blockIdx.y * 32;
#pragma unroll
    for (int k = 0; k < 4; k++) {
        int b = b0 + threadIdx.y + k * 8, i = i0 + threadIdx.x;
        if (i < N_ITEMS) tile[threadIdx.y + k * 8][threadIdx.x] = src[(size_t)b * N_ITEMS + i];
    }
    __syncthreads();
#pragma unroll
    for (int k = 0; k < 4; k++) {
        int i = i0 + threadIdx.y + k * 8, b = b0 + threadIdx.x;
        if (i < N_ITEMS) {
            float v = tile[threadIdx.x][threadIdx.y + k * 8];
            dst [(size_t)i * BATCH + b] = v;
            dsth[(size_t)i * BATCH + b] = __float2half_rn(v * __ldg(&dis[i]));
        }
    }
}

__global__ void transpose_out(const float* __restrict__ src, float* __restrict__ dst)
{
    __shared__ float tile[32][33];
    int i0 = blockIdx.x * 32, b0 = blockIdx.y * 32;
#pragma unroll
    for (int k = 0; k < 4; k++) {
        int i = i0 + threadIdx.y + k * 8, b = b0 + threadIdx.x;
        if (i < N_ITEMS) tile[threadIdx.y + k * 8][threadIdx.x] = src[(size_t)i * BATCH + b];
    }
    __syncthreads();
#pragma unroll
    for (int k = 0; k < 4; k++) {
        int b = b0 + threadIdx.y + k * 8, i = i0 + threadIdx.x;
        if (i < N_ITEMS) dst[(size_t)b * N_ITEMS + i] = tile[threadIdx.x][threadIdx.y + k * 8];
    }
}

// ---------------- CSR/CSC build ----------------------------------------------
__global__ void hist_kernel(const int* __restrict__ row, const int* __restrict__ col,
                            int* __restrict__ degu, int* __restrict__ degi, int nnz)
{
    int e = blockIdx.x * blockDim.x + threadIdx.x;
    if (e >= nnz) return;
    atomicAdd(&degu[row[e]], 1);
    atomicAdd(&degi[col[e]], 1);
}

__device__ __forceinline__ void scan_p1_body(const int* __restrict__ deg,
                                             int* __restrict__ ptr,
                                             int* __restrict__ partial,
                                             int n, int blk)
{
    __shared__ int wsum[8];
    int base = blk * SCAN_T * SCAN_E + threadIdx.x * SCAN_E;
    int v[SCAN_E], t = 0;
#pragma unroll
    for (int k = 0; k < SCAN_E; k++) {
        int i = base + k;
        v[k] = (i < n) ? deg[i] : 0;
        t += v[k];
    }
    int lane = threadIdx.x & 31, wid = threadIdx.x >> 5;
    int s = t;
#pragma unroll
    for (int o = 1; o < 32; o <<= 1) {
        int u = __shfl_up_sync(0xffffffff, s, o);
        if (lane >= o) s += u;
    }
    if (lane == 31) wsum[wid] = s;
    __syncthreads();
    if (wid == 0) {
        int w = (lane < 8) ? wsum[lane] : 0;
#pragma unroll
        for (int o = 1; o < 8; o <<= 1) {
            int u = __shfl_up_sync(0xffffffff, w, o);
            if (lane >= o) w += u;
        }
        if (lane < 8) wsum[lane] = w;
    }
    __syncthreads();
    int run = s - t + (wid ? wsum[wid - 1] : 0);
#pragma unroll
    for (int k = 0; k < SCAN_E; k++) {
        int i = base + k;
        if (i < n) ptr[i] = run;
        run += v[k];
    }
    if (threadIdx.x == SCAN_T - 1) partial[blk] = wsum[7];
}

__global__ void scan_phase1_fused(const int* __restrict__ du, int* __restrict__ pu,
                                  const int* __restrict__ di, int* __restrict__ pi,
                                  int* __restrict__ partial)
{
    int b = blockIdx.x;
    if (b < NBU) scan_p1_body(du, pu, partial,      N_USERS, b);
    else         scan_p1_body(di, pi, partial + 64, N_ITEMS, b - NBU);
}

__device__ __forceinline__ void scan_p2_body(int* partial, int nb, int lane)
{
    int a = (lane < nb) ? partial[lane] : 0;
    int b = (lane + 32 < nb) ? partial[lane + 32] : 0;
    int sa = a, sb = b;
#pragma unroll
    for (int o = 1; o < 32; o <<= 1) {
        int u = __shfl_up_sync(0xffffffff, sa, o); if (lane >= o) sa += u;
        int w = __shfl_up_sync(0xffffffff, sb, o); if (lane >= o) sb += w;
    }
    int tot_a = __shfl_sync(0xffffffff, sa, 31);
    if (lane < nb)      partial[lane]      = sa - a;
    if (lane + 32 < nb) partial[lane + 32] = sb - b + tot_a;
}

__global__ void scan_phase2_fused(int* partial)
{
    int w = threadIdx.x >> 5, lane = threadIdx.x & 31;
    if (w == 0) scan_p2_body(partial,      NBU, lane);
    else        scan_p2_body(partial + 64, NBI, lane);
}

__device__ __forceinline__ void scan_p3_body(int* __restrict__ ptr, int* __restrict__ cursor,
                                             const int* __restrict__ partial,
                                             int n, int total, int blk)
{
    int i = blk * 1024 + threadIdx.x * 4;
    if (i < n) {
        int off = partial[i / (SCAN_T * SCAN_E)];
#pragma unroll
        for (int k = 0; k < 4; k++) {
            int j = i + k;
            if (j < n) { int p = ptr[j] + off; ptr[j] = p; cursor[j] = p; }
        }
    }
    if (blk == 0 && threadIdx.x == 0) ptr[n] = total;
}

__global__ void scan_phase3_fused(int* __restrict__ pu, int* __restrict__ cu,
                                  int* __restrict__ pi, int* __restrict__ ci,
                                  const int* __restrict__ partial, int nnz)
{
    int b = blockIdx.x;
    if (b < P3U) scan_p3_body(pu, cu, partial,      N_USERS, nnz, b);
    else         scan_p3_body(pi, ci, partial + 64, N_ITEMS, nnz, b - P3U);
}

// user scale = 1/du (du_is applied twice); item scale = di^-1/2
__global__ void scale_kernel(const int* __restrict__ pu, float* __restrict__ dui,
                             const int* __restrict__ pi, float* __restrict__ dis)
{
    int i = blockIdx.x * blockDim.x + threadIdx.x;
    if (i < N_USERS) {
        int d = pu[i + 1] - pu[i];
        dui[i] = (d > 0) ? 1.0f / (float)d : 0.f;
    }
    int k = i - N_USERS;
    if (k >= 0 && k < N_ITEMS) {
        int d = pi[k + 1] - pi[k];
        dis[k] = (d > 0) ? rsqrtf((float)d) : 0.f;
    }
}

__global__ void build_lists(const int* __restrict__ row, const int* __restrict__ col,
                            int* __restrict__ cu, int* __restrict__ ci,
                            int* __restrict__ evr, int* __restrict__ evc, int nnz)
{
    int e = blockIdx.x * blockDim.x + threadIdx.x;
    if (e >= nnz) return;
    int r = row[e], c = col[e];
    int pu = atomicAdd(&cu[r], 1);
    evr[pu] = c;
    int pc = atomicAdd(&ci[c], 1);
    evc[pc] = r;
}

// ---------------- degree sort (descending) ------------------------------------
// key = 255 - min(deg,255): ascending counting sort by key == descending by deg.
__device__ __forceinline__ void sort_hist_body(const int* __restrict__ ptr,
                                               int* __restrict__ lh, int n, int blk)
{
    __shared__ int sh[256];
    sh[threadIdx.x] = 0;
    __syncthreads();
    int base = blk * (SCAN_T * SCAN_E);
#pragma unroll
    for (int k = 0; k < SCAN_E; k++) {
        int i = base + threadIdx.x + k * SCAN_T;
        if (i < n) {
            int d = __ldg(&ptr[i + 1]) - __ldg(&ptr[i]);
            int key = 255 - min(d, 255);
            atomicAdd(&sh[key], 1);
        }
    }
    __syncthreads();
    lh[blk * 256 + threadIdx.x] = sh[threadIdx.x];
}

__global__ void sort_hist_fused(const int* __restrict__ pu, int* __restrict__ lhu,
                                const int* __restrict__ pi, int* __restrict__ lhi)
{
    int b = blockIdx.x;
    if (b < NBU) sort_hist_body(pu, lhu, N_USERS, b);
    else         sort_hist_body(pi, lhi, N_ITEMS, b - NBU);
}

// one block per side: turn per-block histograms into per-(block,key) start offsets
__global__ void sort_offsets(int* __restrict__ lhu, int* __restrict__ lhi)
{
    int* lh = (blockIdx.x == 0) ? lhu : lhi;
    int  nb = (blockIdx.x == 0) ? NBU : NBI;
    int  k  = threadIdx.x;

    int tot = 0;
    for (int b = 0; b < nb; b++) tot += lh[b * 256 + k];

    // exclusive scan of tot over the 256 keys
    __shared__ int wsum[8];
    int lane = k & 31, wid = k >> 5;
    int s = tot;
#pragma unroll
    for (int o = 1; o < 32; o <<= 1) {
        int u = __shfl_up_sync(0xffffffff, s, o);
        if (lane >= o) s += u;
    }
    if (lane == 31) wsum[wid] = s;
    __syncthreads();
    if (wid == 0) {
        int w = (lane < 8) ? wsum[lane] : 0;
#pragma unroll
        for (int o = 1; o < 8; o <<= 1) {
            int u = __shfl_up_sync(0xffffffff, w, o);
            if (lane >= o) w += u;
        }
        if (lane < 8) wsum[lane] = w;
    }
    __syncthreads();
    int keystart = s - tot + (wid ? wsum[wid - 1] : 0);

    int run = keystart;
    for (int b = 0; b < nb; b++) {
        int t = lh[b * 256 + k];
        lh[b * 256 + k] = run;
        run += t;
    }
}

__device__ __forceinline__ void sort_scatter_body(const int* __restrict__ ptr,
                                                  const int* __restrict__ lh,
                                                  int* __restrict__ perm, int n, int blk)
{
    __shared__ int cur[256];
    cur[threadIdx.x] = lh[blk * 256 + threadIdx.x];
    __syncthreads();
    int base = blk * (SCAN_T * SCAN_E);
#pragma unroll
    for (int k = 0; k < SCAN_E; k++) {
        int i = base + threadIdx.x + k * SCAN_T;
        if (i < n) {
            int d = __ldg(&ptr[i + 1]) - __ldg(&ptr[i]);
            int key = 255 - min(d, 255);
            int pos = atomicAdd(&cur[key], 1);
            perm[pos] = i;
        }
    }
}

__global__ void sort_scatter_fused(const int* __restrict__ pu, const int* __restrict__ lhu,
                                   int* __restrict__ permu,
                                   const int* __restrict__ pi, const int* __restrict__ lhi,
                                   int* __restrict__ permi)
{
    int b = blockIdx.x;
    if (b < NBU) sort_scatter_body(pu, lhu, permu, N_USERS, b);
    else         sort_scatter_body(pi, lhi, permi, N_ITEMS, b - NBU);
}

// ---------------- wide gather core --------------------------------------------
// One warp per row. 8-lane groups: group g = lane>>3 handles edge j+g, slice
// sl = lane&7 covers halves [8sl, 8sl+8) of the 128B row. 4 edges per iter,
// unroll 2 (proven; deeper unroll and sw-pipelining both regressed).
struct Acc8 { float a[8]; };

__device__ __forceinline__ Acc8 gather_row(const __half* __restrict__ xh,
                                           const int* __restrict__ ev,
                                           int j0, int e, int g, int sl)
{
    Acc8 r;
#pragma unroll
    for (int k = 0; k < 8; k++) r.a[k] = 0.f;
#pragma unroll 2
    for (int j = j0 + g; j < e; j += 4) {
        int idx = __ldg(&ev[j]);
        uint4 q = __ldg((const uint4*)(xh + ((size_t)idx << 6)) + sl);
        float2 f0 = __half22float2(*(__half2*)&q.x);
        float2 f1 = __half22float2(*(__half2*)&q.y);
        float2 f2 = __half22float2(*(__half2*)&q.z);
        float2 f3 = __half22float2(*(__half2*)&q.w);
        r.a[0] += f0.x; r.a[1] += f0.y;
        r.a[2] += f1.x; r.a[3] += f1.y;
        r.a[4] += f2.x; r.a[5] += f2.y;
        r.a[6] += f3.x; r.a[7] += f3.y;
    }
#pragma unroll
    for (int k = 0; k < 8; k++) {
        r.a[k] += __shfl_xor_sync(0xffffffff, r.a[k], 8);
        r.a[k] += __shfl_xor_sync(0xffffffff, r.a[k], 16);
    }
    return r;
}

__device__ __forceinline__ uint4 pack_half8_scaled(const Acc8& r, float s)
{
    uint4 o;
    *(__half2*)&o.x = __floats2half2_rn(s * r.a[0], s * r.a[1]);
    *(__half2*)&o.y = __floats2half2_rn(s * r.a[2], s * r.a[3]);
    *(__half2*)&o.z = __floats2half2_rn(s * r.a[4], s * r.a[5]);
    *(__half2*)&o.w = __floats2half2_rn(s * r.a[6], s * r.a[7]);
    return o;
}

// user side: yh[r] = half( (1/du[r]) * sum_j th[col_j] ), rows in perm order
__global__ void __launch_bounds__(SPMM_T) spmm_user(
    const __half* __restrict__ xh, __half* __restrict__ yh,
    const int* __restrict__ ev, const int* __restrict__ ptr,
    const float* __restrict__ dui, const int* __restrict__ perm)
{
    int rid = blockIdx.x * SPMM_ROWS + (threadIdx.x >> 5);
    if (rid >= N_USERS) return;
    int r = __ldg(&perm[rid]);
    int lane = threadIdx.x & 31, g = lane >> 3, sl = lane & 7;
    int j0 = __ldg(&ptr[r]), e = __ldg(&ptr[r + 1]);
    Acc8 s = gather_row(xh, ev, j0, e, g, sl);
    if (g == 0)
        ((uint4*)(yh + ((size_t)r << 6)))[sl] = pack_half8_scaled(s, __ldg(&dui[r]));
}

// item side, first lap: z = dis[r]*sum(yh); t1 = t0 - 2z; acc = c0*t0 + c1*t1;
// th = half(dis[r]*t1)
__global__ void __launch_bounds__(SPMM_T) spmm_item_first(
    const __half* __restrict__ yh, const int* __restrict__ ev, const int* __restrict__ ptr,
    const float* __restrict__ t0, float* __restrict__ t1, float* __restrict__ acc,
    __half* __restrict__ th, const float* __restrict__ dis, float c0, float c1,
    const int* __restrict__ perm)
{
    int rid = blockIdx.x * SPMM_ROWS + (threadIdx.x >> 5);
    if (rid >= N_ITEMS) return;
    int r = __ldg(&perm[rid]);
    int lane = threadIdx.x & 31, g = lane >> 3, sl = lane & 7;
    int j0 = __ldg(&ptr[r]), e = __ldg(&ptr[r + 1]);
    Acc8 z = gather_row(yh, ev, j0, e, g, sl);
    if (g == 0) {
        float d = __ldg(&dis[r]);
        size_t o = ((size_t)r << 6) + (size_t)sl * 8;
        Acc8 b;
#pragma unroll
        for (int h = 0; h < 2; h++) {
            float4 a = *(const float4*)(t0 + o + h * 4);
            float4 bb, oo;
            bb.x = a.x - 2.f * (d * z.a[h*4+0]); bb.y = a.y - 2.f * (d * z.a[h*4+1]);
            bb.z = a.z - 2.f * (d * z.a[h*4+2]); bb.w = a.w - 2.f * (d * z.a[h*4+3]);
            *(float4*)(t1 + o + h * 4) = bb;
            oo.x = c0 * a.x + c1 * bb.x; oo.y = c0 * a.y + c1 * bb.y;
            oo.z = c0 * a.z + c1 * bb.z; oo.w = c0 * a.w + c1 * bb.w;
            *(float4*)(acc + o + h * 4) = oo;
            b.a[h*4+0] = bb.x; b.a[h*4+1] = bb.y; b.a[h*4+2] = bb.z; b.a[h*4+3] = bb.w;
        }
        *(uint4*)(th + o) = pack_half8_scaled(b, d);
    }
}

// item side, step: z = dis[r]*sum(yh); t2 = 2*t1 - 4z - t0 (in place over t0);
// if do_acc: acc += ca*t1 + cb*t2 ; if !last: write t0io, th = half(dis*t2)
__global__ void __launch_bounds__(SPMM_T) spmm_item_step(
    const __half* __restrict__ yh, const int* __restrict__ ev, const int* __restrict__ ptr,
    float* __restrict__ t0io, const float* __restrict__ t1, float* __restrict__ acc,
    __half* __restrict__ th, const float* __restrict__ dis,
    float ca, float cb, int do_acc, int last, const int* __restrict__ perm)
{
    int rid = blockIdx.x * SPMM_ROWS + (threadIdx.x >> 5);
    if (rid >= N_ITEMS) return;
    int r = __ldg(&perm[rid]);
    int lane = threadIdx.x & 31, g = lane >> 3, sl = lane & 7;
    int j0 = __ldg(&ptr[r]), e = __ldg(&ptr[r + 1]);
    Acc8 z = gather_row(yh, ev, j0, e, g, sl);
    if (g == 0) {
        float d = __ldg(&dis[r]);
        size_t o = ((size_t)r << 6) + (size_t)sl * 8;
        Acc8 t2;
#pragma unroll
        for (int h = 0; h < 2; h++) {
            float4 a = *(const float4*)(t0io + o + h * 4);
            float4 b = *(const float4*)(t1 + o + h * 4);
            float4 t;
            t.x = 2.f * b.x - 4.f * (d * z.a[h*4+0]) - a.x;
            t.y = 2.f * b.y - 4.f * (d * z.a[h*4+1]) - a.y;
            t.z = 2.f * b.z - 4.f * (d * z.a[h*4+2]) - a.z;
            t.w = 2.f * b.w - 4.f * (d * z.a[h*4+3]) - a.w;
            if (!last) *(float4*)(t0io + o + h * 4) = t;
            if (do_acc) {
                float4 oc = *(const float4*)(acc + o + h * 4);
                oc.x += ca * b.x + cb * t.x;
                oc.y += ca * b.y + cb * t.y;
                oc.z += ca * b.z + cb * t.z;
                oc.w += ca * b.w + cb * t.w;
                *(float4*)(acc + o + h * 4) = oc;
            }
            t2.a[h*4+0] = t.x; t2.a[h*4+1] = t.y; t2.a[h*4+2] = t.z; t2.a[h*4+3] = t.w;
        }
        if (!last) *(uint4*)(th + o) = pack_half8_scaled(t2, d);
    }
}

// ---------------- host: replicate cheby_coeffs in double ----------------------
static void compute_coeffs(float c[ORDER + 1])
{
    const int order = ORDER;
    double tgt[ORDER + 1], nodes[ORDER + 1];
    for (int x = 0; x <= order; x++) {
        double v = cos((double)(order - x) / order * M_PI);
        v = nearbyint(v * 1000.0) / 1000.0;
        double t = (v < 0.0) ? pow(-v, (double)FLATNESS) * 0.5 + 0.5
                             : pow(v, (double)FLATNESS) * (-0.5) + 0.5;
        tgt[x] = nearbyint(t * 1000.0) / 1000.0;
    }
    for (int k = 1; k <= order + 1; k++)
        nodes[k - 1] = cos((order + 1 + 0.5 - k) / (double)(order + 1) * M_PI);

    double P0[ORDER + 1], P1[ORDER + 1], P2[ORDER + 1];
    double s0 = 0.0, s1 = 0.0;
    for (int i = 0; i <= order; i++) {
        P0[i] = tgt[i];
        P1[i] = nodes[i] * tgt[i];
        s0 += P0[i]; s1 += P1[i];
    }
    c[0] = (float)(s0 * (2.0 / (order + 1)) / 2.0);
    c[1] = (float)(s1 * (2.0 / (order + 1)));
    for (int k = 2; k <= order; k++) {
        double s = 0.0;
        for (int i = 0; i <= order; i++) {
            P2[i] = 2.0 * nodes[i] * P1[i] - P0[i];
            s += P2[i];
        }
        c[k] = (float)(s * (2.0 / (order + 1)));
        for (int i = 0; i <= order; i++) { P0[i] = P1[i]; P1[i] = P2[i]; }
    }
}

// ---------------- launch ------------------------------------------------------
extern "C" void kernel_launch(void* const* d_in, const int* in_sizes, int n_in,
                              void* d_out, int out_size)
{
    const float* signal = (const float*)d_in[0];
    const int*   row    = (const int*)d_in[2];
    const int*   col    = (const int*)d_in[3];
    const int    nnz    = in_sizes[1];

    float c[ORDER + 1];
    compute_coeffs(c);

    float *ta, *tb, *acc, *dui, *dis;
    __half *yh, *th;
    int *ptru, *ptri, *curu, *curi, *part, *evr, *evc;
    int *lhu, *lhi, *permu, *permi;
    cudaGetSymbolAddress((void**)&ta,    g_ta);
    cudaGetSymbolAddress((void**)&tb,    g_tb);
    cudaGetSymbolAddress((void**)&acc,   g_acc);
    cudaGetSymbolAddress((void**)&yh,    g_yh);
    cudaGetSymbolAddress((void**)&th,    g_th);
    cudaGetSymbolAddress((void**)&ptru,  g_ptru);
    cudaGetSymbolAddress((void**)&ptri,  g_ptri);
    cudaGetSymbolAddress((void**)&curu,  g_curu);
    cudaGetSymbolAddress((void**)&curi,  g_curi);
    cudaGetSymbolAddress((void**)&part,  g_part);
    cudaGetSymbolAddress((void**)&dui,   g_dui);
    cudaGetSymbolAddress((void**)&dis,   g_dis);
    cudaGetSymbolAddress((void**)&evr,   g_evr);
    cudaGetSymbolAddress((void**)&evc,   g_evc);
    cudaGetSymbolAddress((void**)&lhu,   g_lhu);
    cudaGetSymbolAddress((void**)&lhi,   g_lhi);
    cudaGetSymbolAddress((void**)&permu, g_permu);
    cudaGetSymbolAddress((void**)&permi, g_permi);

    dim3 tblk(32, 8);
    dim3 tgrd((N_ITEMS + 31) / 32, (BATCH + 31) / 32);

    const int eblk = (nnz + 255) / 256;
    const int gu   = (N_USERS + SPMM_ROWS - 1) / SPMM_ROWS;
    const int gi   = (N_ITEMS + SPMM_ROWS - 1) / SPMM_ROWS;
    const int sblk = (N_USERS + N_ITEMS + 255) / 256;

    // ---- preprocessing: CSR (by user) + CSC (by item), fused scans ----
    cudaMemsetAsync(curu, 0, sizeof(int) * N_USERS);
    cudaMemsetAsync(curi, 0, sizeof(int) * N_ITEMS);
    hist_kernel<<<eblk, 256>>>(row, col, curu, curi, nnz);
    scan_phase1_fused<<<NBU + NBI, SCAN_T>>>(curu, ptru, curi, ptri, part);
    scan_phase2_fused<<<1, 64>>>(part);
    scan_phase3_fused<<<P3U + P3I, SCAN_T>>>(ptru, curu, ptri, curi, part, nnz);
    scale_kernel<<<sblk, 256>>>(ptru, dui, ptri, dis);
    build_lists<<<eblk, 256>>>(row, col, curu, curi, evr, evc, nnz);

    // ---- degree sort (descending) for tail/imbalance reduction ----
    sort_hist_fused<<<NBU + NBI, 256>>>(ptru, lhu, ptri, lhi);
    sort_offsets<<<2, 256>>>(lhu, lhi);
    sort_scatter_fused<<<NBU + NBI, 256>>>(ptru, lhu, permu, ptri, lhi, permi);

    // ---- signal to item-major (fp32 state + di_is-scaled half shadow) ----
    transpose_in<<<tgrd, tblk>>>(signal, ta, th, dis);

    // ---- Chebyshev recurrence, 8 laps ----
    spmm_user<<<gu, SPMM_T>>>(th, yh, evr, ptru, dui, permu);
    spmm_item_first<<<gi, SPMM_T>>>(yh, evc, ptri, ta, tb, acc, th, dis,
                                    c[0], c[1], permi);

    float* p0 = ta;   // t_{k-2}
    float* p1 = tb;   // t_{k-1}
    for (int k = 2; k <= ORDER; k++) {
        spmm_user<<<gu, SPMM_T>>>(th, yh, evr, ptru, dui, permu);
        int   last   = (k == ORDER);
        int   pair   = (k & 1);               // odd step: fold in c[k-1]*t1 too
        int   do_acc = pair || last;
        float ca     = pair ? c[k - 1] : 0.f;
        float cb     = do_acc ? c[k] : 0.f;
        spmm_item_step<<<gi, SPMM_T>>>(yh, evc, ptri, p0, p1, acc, th, dis,
                                       ca, cb, do_acc, last, permi);
        float* t = p0; p0 = p1; p1 = t;
    }

    transpose_out<<<tgrd, tblk>>>(acc, (float*)d_out);
}